// round 15
// baseline (speedup 1.0000x reference)
#include <cuda_runtime.h>
#include <cuda_bf16.h>
#include <math.h>
#include <stdint.h>

typedef __nv_bfloat16 bf16;

// ---------------- problem constants ----------------
static constexpr int Bn  = 4;
static constexpr int Sn  = 2048;
static constexpr int Hn  = 16;
static constexpr int Mtot = Bn * Sn;  // 8192
static constexpr float SCALE_ = 0.10206207261596575f;  // 1/sqrt(96)

// ---------------- scratch (device globals) ----------------
__device__ bf16 g_cqh[Mtot * 128],  g_cql[Mtot * 128];
__device__ bf16 g_ckvh[Mtot * 128], g_ckvl[Mtot * 128];
__device__ bf16 g_Qh[(size_t)Bn * Hn * Sn * 96], g_Ql[(size_t)Bn * Hn * Sn * 96];
__device__ bf16 g_Kh[(size_t)Bn * Hn * Sn * 96], g_Kl[(size_t)Bn * Hn * Sn * 96];
__device__ bf16 g_Vh[(size_t)Bn * Hn * Sn * 64], g_Vl[(size_t)Bn * Hn * Sn * 64];
__device__ bf16 g_aoh[Mtot * 1024], g_aol[Mtot * 1024];
__device__ float g_cos[Sn * 16], g_sin[Sn * 16];
// packed split weights
__device__ bf16 g_wcath[1024 * 320], g_wcatl[1024 * 320];   // [W_dq | W_dkv | W_kr | 0]
__device__ float g_bcat[320];
__device__ bf16 g_w2qh[128 * 1536], g_w2ql[128 * 1536];     // [W_uq | W_qr]
__device__ float g_b2q[1536];
__device__ bf16 g_w2kh[128 * 2048], g_w2kl[128 * 2048];     // [W_uk | W_uv]
__device__ float g_b2k[2048];
__device__ bf16 g_woh[1024 * 1024], g_wol[1024 * 1024];

// ---------------- PTX helpers (baseline ISA only) ----------------
__device__ __forceinline__ uint32_t smem_u32(const void* p) {
    uint32_t a;
    asm("{ .reg .u64 t; cvta.to.shared.u64 t, %1; cvt.u32.u64 %0, t; }" : "=r"(a) : "l"(p));
    return a;
}
__device__ __forceinline__ void ldm4(uint32_t* r, uint32_t a) {
    asm volatile("ldmatrix.sync.aligned.m8n8.x4.shared.b16 {%0,%1,%2,%3}, [%4];"
                 : "=r"(r[0]), "=r"(r[1]), "=r"(r[2]), "=r"(r[3]) : "r"(a));
}
__device__ __forceinline__ void ldm4t(uint32_t* r, uint32_t a) {
    asm volatile("ldmatrix.sync.aligned.m8n8.x4.trans.shared.b16 {%0,%1,%2,%3}, [%4];"
                 : "=r"(r[0]), "=r"(r[1]), "=r"(r[2]), "=r"(r[3]) : "r"(a));
}
__device__ __forceinline__ void mma_b(float* d, const uint32_t* a, uint32_t b0, uint32_t b1) {
    asm volatile("mma.sync.aligned.m16n8k16.row.col.f32.bf16.bf16.f32 "
                 "{%0,%1,%2,%3}, {%4,%5,%6,%7}, {%8,%9}, {%0,%1,%2,%3};"
                 : "+f"(d[0]), "+f"(d[1]), "+f"(d[2]), "+f"(d[3])
                 : "r"(a[0]), "r"(a[1]), "r"(a[2]), "r"(a[3]), "r"(b0), "r"(b1));
}
__device__ __forceinline__ void cpa16(uint32_t dst, const void* src) {
    asm volatile("cp.async.cg.shared.global [%0], [%1], 16;" :: "r"(dst), "l"(src));
}
#define CP_COMMIT() asm volatile("cp.async.commit_group;" ::: "memory")
#define CP_WAIT0()  asm volatile("cp.async.wait_group 0;" ::: "memory")
#define CP_WAIT1()  asm volatile("cp.async.wait_group 1;" ::: "memory")

__device__ __forceinline__ uint32_t packbf(float x, float y) {
    __nv_bfloat162 t = __floats2bfloat162_rn(x, y);
    return *reinterpret_cast<uint32_t*>(&t);
}
__device__ __forceinline__ uint32_t packlo(float x, float y, uint32_t h) {
    __nv_bfloat162 hh = *reinterpret_cast<__nv_bfloat162*>(&h);
    float2 f = __bfloat1622float2(hh);
    return packbf(x - f.x, y - f.y);
}
__device__ __forceinline__ void cvt4(float4 v, uint2& h, uint2& l) {
    __nv_bfloat162 h0 = __floats2bfloat162_rn(v.x, v.y);
    __nv_bfloat162 h1 = __floats2bfloat162_rn(v.z, v.w);
    float2 f0 = __bfloat1622float2(h0), f1 = __bfloat1622float2(h1);
    __nv_bfloat162 l0 = __floats2bfloat162_rn(v.x - f0.x, v.y - f0.y);
    __nv_bfloat162 l1 = __floats2bfloat162_rn(v.z - f1.x, v.w - f1.y);
    h = make_uint2(*(uint32_t*)&h0, *(uint32_t*)&h1);
    l = make_uint2(*(uint32_t*)&l0, *(uint32_t*)&l1);
}

// ---------------- fused prep: rope tables + all weight packs + W_o split ----------
__global__ void prep_kernel(
    const float* __restrict__ Wdq, const float* __restrict__ Wdkv,
    const float* __restrict__ Wkr,
    const float* __restrict__ bdq, const float* __restrict__ bdkv,
    const float* __restrict__ bkr,
    const float* __restrict__ Wuq, const float* __restrict__ Wqr,
    const float* __restrict__ buq, const float* __restrict__ bqr,
    const float* __restrict__ Wuk, const float* __restrict__ Wuv,
    const float* __restrict__ buk, const float* __restrict__ buv,
    const float* __restrict__ Wo,
    float* __restrict__ ct, float* __restrict__ st,
    bf16* __restrict__ w1h, bf16* __restrict__ w1l, float* __restrict__ bcat,
    bf16* __restrict__ w2qh, bf16* __restrict__ w2ql, float* __restrict__ b2q,
    bf16* __restrict__ w2kh, bf16* __restrict__ w2kl, float* __restrict__ b2k,
    bf16* __restrict__ woh, bf16* __restrict__ wol) {
    const int blk = blockIdx.x, t = threadIdx.x;
    if (blk < 128) {
        int i = blk * 256 + t;
        int s = i >> 4, p = i & 15;
        float inv = powf(10000.f, -(float)p / 16.f);
        float c, sn;
        sincosf((float)s * inv, &sn, &c);
        ct[i] = c; st[i] = sn;
    } else if (blk < 1408) {
        int idx = (blk - 128) * 256 + t;
        if (idx < 320)
            bcat[idx] = idx < 128 ? bdq[idx]
                      : (idx < 256 ? bdkv[idx - 128] : (idx < 288 ? bkr[idx - 256] : 0.f));
        if (idx >= 1024 * 320) return;
        int k = idx / 320, n = idx % 320;
        float v = n < 128 ? Wdq[k * 128 + n]
                : (n < 256 ? Wdkv[k * 128 + n - 128]
                : (n < 288 ? Wkr[k * 32 + n - 256] : 0.f));
        bf16 h = __float2bfloat16_rn(v);
        w1h[idx] = h;
        w1l[idx] = __float2bfloat16_rn(v - __bfloat162float(h));
    } else if (blk < 2176) {
        int idx = (blk - 1408) * 256 + t;
        if (idx < 1536) b2q[idx] = idx < 1024 ? buq[idx] : bqr[idx - 1024];
        int k = idx / 1536, n = idx % 1536;
        float v = n < 1024 ? Wuq[k * 1024 + n] : Wqr[k * 512 + (n - 1024)];
        bf16 h = __float2bfloat16_rn(v);
        w2qh[idx] = h;
        w2ql[idx] = __float2bfloat16_rn(v - __bfloat162float(h));
    } else if (blk < 3200) {
        int idx = (blk - 2176) * 256 + t;
        if (idx < 2048) b2k[idx] = idx < 1024 ? buk[idx] : buv[idx - 1024];
        int k = idx / 2048, n = idx % 2048;
        float v = n < 1024 ? Wuk[k * 1024 + n] : Wuv[k * 1024 + (n - 1024)];
        bf16 h = __float2bfloat16_rn(v);
        w2kh[idx] = h;
        w2kl[idx] = __float2bfloat16_rn(v - __bfloat162float(h));
    } else {
        int i = ((blk - 3200) * 256 + t) * 4;
        float4 v = *(const float4*)(Wo + i);
        uint2 h, l; cvt4(v, h, l);
        *(uint2*)(woh + i) = h;
        *(uint2*)(wol + i) = l;
    }
}

// ---------------- split-bf16 mma.sync GEMM, templated BK, cp.async pipelined ----
// MODE 0: fp32 out (+bias)
// MODE 5: fused stage-1: A from fp32 x (reg-pipelined cvt); routing epilogue
// MODE 6: fused stage-2 q routing; MODE 7: fused stage-2 kv routing
// BKT=K (e.g. 128) => single-shot: one load stage, one barrier, no pipeline.
template <int BM, int BN, int WM, int WN, int BKT, int MODE>
__global__ void __launch_bounds__(256)
gemm_sp(const bf16* __restrict__ Ah, const bf16* __restrict__ Al,
        const float* __restrict__ Af,
        const bf16* __restrict__ Bh, const bf16* __restrict__ Bl,
        const float* __restrict__ bias, float scale,
        float* __restrict__ Cf, bf16* __restrict__ Coh, bf16* __restrict__ Col,
        bf16* __restrict__ Coh2, bf16* __restrict__ Col2,
        bf16* __restrict__ Koh, bf16* __restrict__ Kol,
        const float* __restrict__ ct, const float* __restrict__ st,
        int M, int N, int K) {
    constexpr int BK = BKT, ASTR = BK + 8, BSTR = BN + 8;
    constexpr int MI = WM / 16, NI = WN / 8, WNC = BN / WN;
    constexpr int ASZ = BM * ASTR, BSZ = BK * BSTR;
    constexpr int STG = 2 * (ASZ + BSZ);
    constexpr int KQ = BK / 8;
    constexpr int NAR = BM * BK / (4 * 256);

    extern __shared__ bf16 smg[];
    const int tid = threadIdx.x, lane = tid & 31, wid = tid >> 5;
    const int wm0 = (wid / WNC) * WM, wn0 = (wid % WNC) * WN;
    const int m0 = blockIdx.y * BM, n0 = blockIdx.x * BN;
    const uint32_t sb = smem_u32(smg);

    float acc[MI][NI][4];
#pragma unroll
    for (int i = 0; i < MI; i++)
#pragma unroll
        for (int j = 0; j < NI; j++)
#pragma unroll
            for (int q = 0; q < 4; q++) acc[i][j][q] = 0.f;

    const int nch = K / BK;

    auto load_B = [&](int stg, int c) {
        uint32_t pBH = sb + (uint32_t)(stg * STG + 2 * ASZ) * 2;
        uint32_t pBL = pBH + BSZ * 2;
        const bf16* gBh = Bh + (size_t)(c * BK) * N + n0;
        const bf16* gBl = Bl + (size_t)(c * BK) * N + n0;
#pragma unroll
        for (int f = tid; f < BK * (BN / 8); f += 256) {
            int k = f / (BN / 8), n8 = (f % (BN / 8)) * 8;
            uint32_t d = (uint32_t)(k * BSTR + n8) * 2;
            cpa16(pBH + d, gBh + (size_t)k * N + n8);
            cpa16(pBL + d, gBl + (size_t)k * N + n8);
        }
    };
    auto load_A = [&](int stg, int c) {
        uint32_t pAH = sb + (uint32_t)(stg * STG) * 2;
        uint32_t pAL = pAH + ASZ * 2;
        const bf16* gAh = Ah + (size_t)m0 * K + c * BK;
        const bf16* gAl = Al + (size_t)m0 * K + c * BK;
#pragma unroll
        for (int f = tid; f < BM * KQ; f += 256) {
            int m = f / KQ, k8 = (f % KQ) * 8;
            uint32_t d = (uint32_t)(m * ASTR + k8) * 2;
            cpa16(pAH + d, gAh + (size_t)m * K + k8);
            cpa16(pAL + d, gAl + (size_t)m * K + k8);
        }
    };

    float4 Areg[NAR > 0 ? NAR : 1];
    auto ldA_f32 = [&](int c) {
        const float* g = Af + (size_t)m0 * K + c * BK;
#pragma unroll
        for (int i = 0; i < NAR; i++) {
            int f = tid + i * 256;
            int m = f / (BK / 4), k4 = (f % (BK / 4)) * 4;
            Areg[i] = *(const float4*)(g + (size_t)m * K + k4);
        }
    };

    if constexpr (MODE == 5) {
        ldA_f32(0);
        load_B(0, 0);
        CP_COMMIT();
    } else {
        load_A(0, 0);
        load_B(0, 0);
        CP_COMMIT();
    }

    for (int c = 0; c < nch; c++) {
        const int cur = c & 1;
        if constexpr (MODE == 5) {
            {
                uint32_t pAH = sb + (uint32_t)(cur * STG) * 2;
                uint32_t pAL = pAH + ASZ * 2;
#pragma unroll
                for (int i = 0; i < NAR; i++) {
                    int f = tid + i * 256;
                    int m = f / (BK / 4), k4 = (f % (BK / 4)) * 4;
                    uint2 h, l; cvt4(Areg[i], h, l);
                    uint32_t d = (uint32_t)(m * ASTR + k4) * 2;
                    asm volatile("st.shared.v2.b32 [%0], {%1, %2};" :: "r"(pAH + d), "r"(h.x), "r"(h.y));
                    asm volatile("st.shared.v2.b32 [%0], {%1, %2};" :: "r"(pAL + d), "r"(l.x), "r"(l.y));
                }
            }
            if (c + 1 < nch) { ldA_f32(c + 1); load_B(cur ^ 1, c + 1); CP_COMMIT(); CP_WAIT1(); }
            else             { CP_WAIT0(); }
        } else {
            if (c + 1 < nch) { load_A(cur ^ 1, c + 1); load_B(cur ^ 1, c + 1); CP_COMMIT(); CP_WAIT1(); }
            else             { CP_WAIT0(); }
        }
        __syncthreads();

        const uint32_t base = sb + (uint32_t)(cur * STG) * 2;
        const uint32_t aAH = base;
        const uint32_t aAL = aAH + ASZ * 2;
        const uint32_t aBH = aAL + ASZ * 2;
        const uint32_t aBL = aBH + BSZ * 2;

#pragma unroll
        for (int kk = 0; kk < BK; kk += 16) {
            uint32_t aH[MI][4], aL[MI][4];
#pragma unroll
            for (int mi = 0; mi < MI; mi++) {
                uint32_t off = (uint32_t)((wm0 + mi * 16 + (lane & 15)) * ASTR
                                          + kk + ((lane >> 4) << 3)) * 2;
                ldm4(aH[mi], aAH + off);
                ldm4(aL[mi], aAL + off);
            }
            uint32_t bH[NI][2], bL[NI][2];
#pragma unroll
            for (int nj = 0; nj < NI / 2; nj++) {
                uint32_t off = (uint32_t)((kk + ((lane >> 4) << 3) + (lane & 7)) * BSTR
                                          + wn0 + nj * 16 + (((lane >> 3) & 1) << 3)) * 2;
                uint32_t r[4];
                ldm4t(r, aBH + off);
                bH[2 * nj][0] = r[0]; bH[2 * nj][1] = r[2];
                bH[2 * nj + 1][0] = r[1]; bH[2 * nj + 1][1] = r[3];
                ldm4t(r, aBL + off);
                bL[2 * nj][0] = r[0]; bL[2 * nj][1] = r[2];
                bL[2 * nj + 1][0] = r[1]; bL[2 * nj + 1][1] = r[3];
            }
#pragma unroll
            for (int mi = 0; mi < MI; mi++)
#pragma unroll
                for (int ni = 0; ni < NI; ni++) {
                    mma_b(acc[mi][ni], aH[mi], bH[ni][0], bH[ni][1]);
                    mma_b(acc[mi][ni], aH[mi], bL[ni][0], bL[ni][1]);
                    mma_b(acc[mi][ni], aL[mi], bH[ni][0], bH[ni][1]);
                }
        }
        if (c + 1 < nch) __syncthreads();
    }

    // ---------------- fused epilogue ----------------
#pragma unroll
    for (int mi = 0; mi < MI; mi++) {
        int r0 = m0 + wm0 + mi * 16 + (lane >> 2);
#pragma unroll
        for (int ni = 0; ni < NI; ni++) {
            int cc = n0 + wn0 + ni * 8 + (lane & 3) * 2;
            float bx = bias[cc], by = bias[cc + 1];
            float x0 = acc[mi][ni][0] + bx, y0 = acc[mi][ni][1] + by;
            float x1 = acc[mi][ni][2] + bx, y1 = acc[mi][ni][3] + by;

            if constexpr (MODE == 0) {
                *(float2*)(Cf + (size_t)r0 * N + cc) = make_float2(x0, y0);
                *(float2*)(Cf + (size_t)(r0 + 8) * N + cc) = make_float2(x1, y1);
            } else if constexpr (MODE == 5) {
                if (cc < 128) {
                    size_t d0 = (size_t)r0 * 128 + cc;
                    size_t d1 = d0 + (size_t)8 * 128;
                    uint32_t hh = packbf(x0, y0);
                    *(uint32_t*)(Coh + d0) = hh;
                    *(uint32_t*)(Col + d0) = packlo(x0, y0, hh);
                    hh = packbf(x1, y1);
                    *(uint32_t*)(Coh + d1) = hh;
                    *(uint32_t*)(Col + d1) = packlo(x1, y1, hh);
                } else if (cc < 256) {
                    size_t d0 = (size_t)r0 * 128 + (cc - 128);
                    size_t d1 = d0 + (size_t)8 * 128;
                    uint32_t hh = packbf(x0, y0);
                    *(uint32_t*)(Coh2 + d0) = hh;
                    *(uint32_t*)(Col2 + d0) = packlo(x0, y0, hh);
                    hh = packbf(x1, y1);
                    *(uint32_t*)(Coh2 + d1) = hh;
                    *(uint32_t*)(Col2 + d1) = packlo(x1, y1, hh);
                } else if (cc < 288) {
                    int b = r0 >> 11, s = r0 & 2047;
                    int pp = cc - 256, p = pp >> 1;
                    float c0 = ct[s * 16 + p], s0 = st[s * 16 + p];
                    float k0 = x0 * c0 - y0 * s0, k1 = x0 * s0 + y0 * c0;
                    uint32_t hh0 = packbf(k0, k1), ll0 = packlo(k0, k1, hh0);
                    float c1 = ct[(s + 8) * 16 + p], s1 = st[(s + 8) * 16 + p];
                    k0 = x1 * c1 - y1 * s1; k1 = x1 * s1 + y1 * c1;
                    uint32_t hh1 = packbf(k0, k1), ll1 = packlo(k0, k1, hh1);
                    size_t rowb = ((size_t)(b * Hn) * Sn + s) * 96 + 64 + pp;
#pragma unroll
                    for (int h = 0; h < Hn; h++) {
                        size_t d0 = rowb + (size_t)h * Sn * 96;
                        *(uint32_t*)(Koh + d0) = hh0;
                        *(uint32_t*)(Kol + d0) = ll0;
                        *(uint32_t*)(Koh + d0 + 8 * 96) = hh1;
                        *(uint32_t*)(Kol + d0 + 8 * 96) = ll1;
                    }
                }
            } else if constexpr (MODE == 6) {
                int b = r0 >> 11, s = r0 & 2047;
                if (cc < 1024) {
                    int h = cc >> 6, d = cc & 63;
                    size_t d0 = ((size_t)((b * Hn + h) * Sn) + s) * 96 + d;
                    size_t d1 = d0 + (size_t)8 * 96;
                    x0 *= scale; y0 *= scale; x1 *= scale; y1 *= scale;
                    uint32_t hh = packbf(x0, y0);
                    *(uint32_t*)(Coh + d0) = hh;
                    *(uint32_t*)(Col + d0) = packlo(x0, y0, hh);
                    hh = packbf(x1, y1);
                    *(uint32_t*)(Coh + d1) = hh;
                    *(uint32_t*)(Col + d1) = packlo(x1, y1, hh);
                } else {
                    int c2 = cc - 1024;
                    int h = c2 >> 5, pp = c2 & 31, p = pp >> 1;
                    size_t d0 = ((size_t)((b * Hn + h) * Sn) + s) * 96 + 64 + pp;
                    size_t d1 = d0 + (size_t)8 * 96;
                    float c0 = ct[s * 16 + p], s0 = st[s * 16 + p];
                    float xr = (x0 * c0 - y0 * s0) * scale;
                    float yr = (x0 * s0 + y0 * c0) * scale;
                    uint32_t hh = packbf(xr, yr);
                    *(uint32_t*)(Coh + d0) = hh;
                    *(uint32_t*)(Col + d0) = packlo(xr, yr, hh);
                    float c1 = ct[(s + 8) * 16 + p], s1 = st[(s + 8) * 16 + p];
                    xr = (x1 * c1 - y1 * s1) * scale;
                    yr = (x1 * s1 + y1 * c1) * scale;
                    hh = packbf(xr, yr);
                    *(uint32_t*)(Coh + d1) = hh;
                    *(uint32_t*)(Col + d1) = packlo(xr, yr, hh);
                }
            } else {  // MODE 7
                int b = r0 >> 11, s = r0 & 2047;
                if (cc < 1024) {
                    int h = cc >> 6, d = cc & 63;
                    size_t d0 = ((size_t)((b * Hn + h) * Sn) + s) * 96 + d;
                    size_t d1 = d0 + (size_t)8 * 96;
                    uint32_t hh = packbf(x0, y0);
                    *(uint32_t*)(Coh + d0) = hh;
                    *(uint32_t*)(Col + d0) = packlo(x0, y0, hh);
                    hh = packbf(x1, y1);
                    *(uint32_t*)(Coh + d1) = hh;
                    *(uint32_t*)(Col + d1) = packlo(x1, y1, hh);
                } else {
                    int c2 = cc - 1024;
                    int h = c2 >> 6, d = c2 & 63;
                    size_t d0 = ((size_t)((b * Hn + h) * Sn) + s) * 64 + d;
                    size_t d1 = d0 + (size_t)8 * 64;
                    uint32_t hh = packbf(x0, y0);
                    *(uint32_t*)(Coh2 + d0) = hh;
                    *(uint32_t*)(Col2 + d0) = packlo(x0, y0, hh);
                    hh = packbf(x1, y1);
                    *(uint32_t*)(Coh2 + d1) = hh;
                    *(uint32_t*)(Col2 + d1) = packlo(x1, y1, hh);
                }
            }
        }
    }
}

// ---------------- flash attention: deferred-consume pipeline, 3 KV buffers ----------
static constexpr int QSf = 104;
static constexpr int VSf = 72;
static constexpr int FL_UQ = 2 * 128 * QSf;
static constexpr int U_KV  = 2 * 64 * QSf + 2 * 64 * VSf;
static constexpr int FL_SMEM = (FL_UQ + 3 * U_KV) * 2;

__global__ void __launch_bounds__(256, 1)
flash_mma(const bf16* __restrict__ Qh, const bf16* __restrict__ Ql,
          const bf16* __restrict__ Kh, const bf16* __restrict__ Kl,
          const bf16* __restrict__ Vh, const bf16* __restrict__ Vl,
          bf16* __restrict__ Ooh, bf16* __restrict__ Ool) {
    extern __shared__ bf16 sm[];

    const int qt = gridDim.x - 1 - blockIdx.x;
    const int bh = blockIdx.y;
    const int tid = threadIdx.x, lane = tid & 31, wid = tid >> 5;
    const int wm = wid * 16;

    const uint32_t sb = smem_u32(sm);
    const uint32_t aQh = sb;
    const uint32_t aQl = aQh + 128 * QSf * 2;

    {
        const bf16* gQh = Qh + ((size_t)bh * Sn + (size_t)qt * 128) * 96;
        const bf16* gQl = Ql + ((size_t)bh * Sn + (size_t)qt * 128) * 96;
#pragma unroll
        for (int f = tid; f < 128 * 12; f += 256) {
            int r = f / 12, c = (f % 12) * 8;
            uint32_t d = (uint32_t)(r * QSf + c) * 2;
            cpa16(aQh + d, gQh + (size_t)r * 96 + c);
            cpa16(aQl + d, gQl + (size_t)r * 96 + c);
        }
        CP_COMMIT();
    }

    auto kvb = [&](int buf) -> uint32_t {
        return sb + (uint32_t)(FL_UQ + buf * U_KV) * 2;
    };
    auto loadKV = [&](int buf, int kt) {
        uint32_t pKh = kvb(buf);
        uint32_t pKl = pKh + (uint32_t)(64 * QSf) * 2;
        uint32_t pVh = pKh + (uint32_t)(2 * 64 * QSf) * 2;
        uint32_t pVl = pVh + (uint32_t)(64 * VSf) * 2;
        const bf16* gKh = Kh + ((size_t)bh * Sn + (size_t)kt * 64) * 96;
        const bf16* gKl = Kl + ((size_t)bh * Sn + (size_t)kt * 64) * 96;
#pragma unroll
        for (int f = tid; f < 64 * 12; f += 256) {
            int r = f / 12, c = (f % 12) * 8;
            uint32_t d = (uint32_t)(r * QSf + c) * 2;
            cpa16(pKh + d, gKh + (size_t)r * 96 + c);
            cpa16(pKl + d, gKl + (size_t)r * 96 + c);
        }
        const bf16* gVh = Vh + ((size_t)bh * Sn + (size_t)kt * 64) * 64;
        const bf16* gVl = Vl + ((size_t)bh * Sn + (size_t)kt * 64) * 64;
#pragma unroll
        for (int f = tid; f < 64 * 8; f += 256) {
            int r = f >> 3, c = (f & 7) * 8;
            uint32_t d = (uint32_t)(r * VSf + c) * 2;
            cpa16(pVh + d, gVh + (size_t)r * 64 + c);
            cpa16(pVl + d, gVl + (size_t)r * 64 + c);
        }
    };

    loadKV(0, 0);
    CP_COMMIT();

    CP_WAIT1();
    __syncthreads();
    uint32_t qhr[6][4], qlr[6][4];
#pragma unroll
    for (int kk = 0; kk < 6; kk++) {
        uint32_t qoff = (uint32_t)((wm + (lane & 15)) * QSf + kk * 16 + ((lane >> 4) << 3)) * 2;
        ldm4(qhr[kk], aQh + qoff);
        ldm4(qlr[kk], aQl + qoff);
    }

    float m0r = -1e30f, m1r = -1e30f, l0r = 0.f, l1r = 0.f;
    float acc[8][4];
#pragma unroll
    for (int i = 0; i < 8; i++)
#pragma unroll
        for (int q = 0; q < 4; q++) acc[i][q] = 0.f;
    float Sp[8][4];

    auto consume = [&](int pbuf) {
        float mt0 = -1e30f, mt1 = -1e30f;
#pragma unroll
        for (int ni = 0; ni < 8; ni++) {
            mt0 = fmaxf(mt0, fmaxf(Sp[ni][0], Sp[ni][1]));
            mt1 = fmaxf(mt1, fmaxf(Sp[ni][2], Sp[ni][3]));
        }
        mt0 = fmaxf(mt0, __shfl_xor_sync(0xffffffff, mt0, 1));
        mt0 = fmaxf(mt0, __shfl_xor_sync(0xffffffff, mt0, 2));
        mt1 = fmaxf(mt1, __shfl_xor_sync(0xffffffff, mt1, 1));
        mt1 = fmaxf(mt1, __shfl_xor_sync(0xffffffff, mt1, 2));
        float mn0 = fmaxf(m0r, mt0), mn1 = fmaxf(m1r, mt1);
        float al0 = __expf(m0r - mn0), al1 = __expf(m1r - mn1);
        m0r = mn0; m1r = mn1;

        float s0 = 0.f, s1 = 0.f;
#pragma unroll
        for (int ni = 0; ni < 8; ni++) {
            Sp[ni][0] = __expf(Sp[ni][0] - mn0); s0 += Sp[ni][0];
            Sp[ni][1] = __expf(Sp[ni][1] - mn0); s0 += Sp[ni][1];
            Sp[ni][2] = __expf(Sp[ni][2] - mn1); s1 += Sp[ni][2];
            Sp[ni][3] = __expf(Sp[ni][3] - mn1); s1 += Sp[ni][3];
        }
        s0 += __shfl_xor_sync(0xffffffff, s0, 1);
        s0 += __shfl_xor_sync(0xffffffff, s0, 2);
        s1 += __shfl_xor_sync(0xffffffff, s1, 1);
        s1 += __shfl_xor_sync(0xffffffff, s1, 2);
        l0r = l0r * al0 + s0;
        l1r = l1r * al1 + s1;
#pragma unroll
        for (int ni = 0; ni < 8; ni++) {
            acc[ni][0] *= al0; acc[ni][1] *= al0;
            acc[ni][2] *= al1; acc[ni][3] *= al1;
        }

        const uint32_t bVh = kvb(pbuf) + (uint32_t)(2 * 64 * QSf) * 2;
        const uint32_t bVl = bVh + (uint32_t)(64 * VSf) * 2;
#pragma unroll
        for (int kp = 0; kp < 4; kp++) {
            uint32_t ah[4], alr[4];
            ah[0]  = packbf(Sp[2 * kp][0],     Sp[2 * kp][1]);
            alr[0] = packlo(Sp[2 * kp][0],     Sp[2 * kp][1],     ah[0]);
            ah[1]  = packbf(Sp[2 * kp][2],     Sp[2 * kp][3]);
            alr[1] = packlo(Sp[2 * kp][2],     Sp[2 * kp][3],     ah[1]);
            ah[2]  = packbf(Sp[2 * kp + 1][0], Sp[2 * kp + 1][1]);
            alr[2] = packlo(Sp[2 * kp + 1][0], Sp[2 * kp + 1][1], ah[2]);
            ah[3]  = packbf(Sp[2 * kp + 1][2], Sp[2 * kp + 1][3]);
            alr[3] = packlo(Sp[2 * kp + 1][2], Sp[2 * kp + 1][3], ah[3]);
#pragma unroll
            for (int ng = 0; ng < 4; ng++) {
                uint32_t voff = (uint32_t)((kp * 16 + (lane & 7) + ((lane >> 4) << 3)) * VSf
                                           + ng * 16 + (((lane >> 3) & 1) << 3)) * 2;
                uint32_t vh[4], vl[4];
                ldm4t(vh, bVh + voff);
                ldm4t(vl, bVl + voff);
                mma_b(acc[2 * ng],     ah,  vh[0], vh[2]);
                mma_b(acc[2 * ng],     ah,  vl[0], vl[2]);
                mma_b(acc[2 * ng],     alr, vh[0], vh[2]);
                mma_b(acc[2 * ng + 1], ah,  vh[1], vh[3]);
                mma_b(acc[2 * ng + 1], ah,  vl[1], vl[3]);
                mma_b(acc[2 * ng + 1], alr, vh[1], vh[3]);
            }
        }
    };

    const int nkt = 2 * qt + 2;
    int cur = 0;
    for (int kt = 0; kt < nkt; kt++) {
        const int nxt = (cur == 2) ? 0 : cur + 1;
        const int prv = (cur == 0) ? 2 : cur - 1;
        if (kt + 1 < nkt) { loadKV(nxt, kt + 1); CP_COMMIT(); CP_WAIT1(); }
        else              { CP_WAIT0(); }
        __syncthreads();

        const uint32_t bKh = kvb(cur);
        const uint32_t bKl = bKh + (uint32_t)(64 * QSf) * 2;
        float S[8][4];
#pragma unroll
        for (int i = 0; i < 8; i++)
#pragma unroll
            for (int q = 0; q < 4; q++) S[i][q] = 0.f;

#pragma unroll
        for (int kk = 0; kk < 6; kk++) {
#pragma unroll
            for (int ng = 0; ng < 4; ng++) {
                uint32_t koff = (uint32_t)((ng * 16 + (lane & 7) + ((lane >> 4) << 3)) * QSf
                                           + kk * 16 + (((lane >> 3) & 1) << 3)) * 2;
                uint32_t kh[4], kl[4];
                ldm4(kh, bKh + koff);
                ldm4(kl, bKl + koff);
                mma_b(S[2 * ng],     qhr[kk], kh[0], kh[1]);
                mma_b(S[2 * ng],     qhr[kk], kl[0], kl[1]);
                mma_b(S[2 * ng],     qlr[kk], kh[0], kh[1]);
                mma_b(S[2 * ng + 1], qhr[kk], kh[2], kh[3]);
                mma_b(S[2 * ng + 1], qhr[kk], kl[2], kl[3]);
                mma_b(S[2 * ng + 1], qlr[kk], kh[2], kh[3]);
            }
        }

        if (kt >= 2 * qt) {
            int qrow0 = qt * 128 + wm + (lane >> 2);
            int kbase = kt * 64 + (lane & 3) * 2;
#pragma unroll
            for (int ni = 0; ni < 8; ni++) {
                int kc = kbase + ni * 8;
                if (kc > qrow0)         S[ni][0] = -1e30f;
                if (kc + 1 > qrow0)     S[ni][1] = -1e30f;
                if (kc > qrow0 + 8)     S[ni][2] = -1e30f;
                if (kc + 1 > qrow0 + 8) S[ni][3] = -1e30f;
            }
        }

        if (kt > 0) consume(prv);

#pragma unroll
        for (int i = 0; i < 8; i++)
#pragma unroll
            for (int q = 0; q < 4; q++) Sp[i][q] = S[i][q];

        cur = nxt;
    }
    consume((cur == 0) ? 2 : cur - 1);

    const int b = bh >> 4, h = bh & 15;
    float inv0 = 1.f / l0r, inv1 = 1.f / l1r;
    int r0 = qt * 128 + wm + (lane >> 2);
    size_t base0 = ((size_t)b * Sn + r0) * 1024 + h * 64 + (lane & 3) * 2;
    size_t base1 = base0 + (size_t)8 * 1024;
#pragma unroll
    for (int ni = 0; ni < 8; ni++) {
        float x = acc[ni][0] * inv0, y = acc[ni][1] * inv0;
        uint32_t hh = packbf(x, y);
        *(uint32_t*)(Ooh + base0 + ni * 8) = hh;
        *(uint32_t*)(Ool + base0 + ni * 8) = packlo(x, y, hh);
        x = acc[ni][2] * inv1; y = acc[ni][3] * inv1;
        hh = packbf(x, y);
        *(uint32_t*)(Ooh + base1 + ni * 8) = hh;
        *(uint32_t*)(Ool + base1 + ni * 8) = packlo(x, y, hh);
    }
}

// ---------------- launch ----------------
extern "C" void kernel_launch(void* const* d_in, const int* in_sizes, int n_in,
                              void* d_out, int out_size) {
    const float* x     = (const float*)d_in[0];
    // d_in[1] = mask: tril of ones -> uniform +1 on allowed entries; softmax is
    // shift-invariant -> plain causal masking. Unused.
    const float* W_dkv = (const float*)d_in[2];
    const float* b_dkv = (const float*)d_in[3];
    const float* W_dq  = (const float*)d_in[4];
    const float* b_dq  = (const float*)d_in[5];
    const float* W_uk  = (const float*)d_in[6];
    const float* b_uk  = (const float*)d_in[7];
    const float* W_uv  = (const float*)d_in[8];
    const float* b_uv  = (const float*)d_in[9];
    const float* W_uq  = (const float*)d_in[10];
    const float* b_uq  = (const float*)d_in[11];
    const float* W_qr  = (const float*)d_in[12];
    const float* b_qr  = (const float*)d_in[13];
    const float* W_kr  = (const float*)d_in[14];
    const float* b_kr  = (const float*)d_in[15];
    const float* W_o   = (const float*)d_in[16];
    const float* b_o   = (const float*)d_in[17];
    float* out = (float*)d_out;

    bf16 *cqh, *cql, *ckvh, *ckvl, *Qh, *Ql, *Kh, *Kl, *Vh, *Vl, *aoh, *aol;
    bf16 *wcath, *wcatl, *w2qh, *w2ql, *w2kh, *w2kl, *woh, *wol;
    float *ct, *st, *bcat, *b2q, *b2k;
    cudaGetSymbolAddress((void**)&cqh, g_cqh); cudaGetSymbolAddress((void**)&cql, g_cql);
    cudaGetSymbolAddress((void**)&ckvh, g_ckvh); cudaGetSymbolAddress((void**)&ckvl, g_ckvl);
    cudaGetSymbolAddress((void**)&Qh, g_Qh);   cudaGetSymbolAddress((void**)&Ql, g_Ql);
    cudaGetSymbolAddress((void**)&Kh, g_Kh);   cudaGetSymbolAddress((void**)&Kl, g_Kl);
    cudaGetSymbolAddress((void**)&Vh, g_Vh);   cudaGetSymbolAddress((void**)&Vl, g_Vl);
    cudaGetSymbolAddress((void**)&aoh, g_aoh); cudaGetSymbolAddress((void**)&aol, g_aol);
    cudaGetSymbolAddress((void**)&ct, g_cos);  cudaGetSymbolAddress((void**)&st, g_sin);
    cudaGetSymbolAddress((void**)&wcath, g_wcath); cudaGetSymbolAddress((void**)&wcatl, g_wcatl);
    cudaGetSymbolAddress((void**)&bcat, g_bcat);
    cudaGetSymbolAddress((void**)&w2qh, g_w2qh);   cudaGetSymbolAddress((void**)&w2ql, g_w2ql);
    cudaGetSymbolAddress((void**)&b2q, g_b2q);
    cudaGetSymbolAddress((void**)&w2kh, g_w2kh);   cudaGetSymbolAddress((void**)&w2kl, g_w2kl);
    cudaGetSymbolAddress((void**)&b2k, g_b2k);
    cudaGetSymbolAddress((void**)&woh, g_woh);     cudaGetSymbolAddress((void**)&wol, g_wol);

    const int M = Mtot;

    // smem sizes
    const int smemB64 = 2 * 2 * (128 * 72 + 64 * 72) * 2;   // 110592 (BK=64, 2 stages)
    const int smemS1  = 2 * 2 * (64 * 72 + 64 * 72) * 2;    //  73728 (BK=64, 2 stages)
    const int smemS2  = 2 * (128 * 136 + 128 * 72) * 2;     // 106496 (BK=128, 1 stage)
    cudaFuncSetAttribute((const void*)gemm_sp<64, 64, 16, 32, 64, 5>,
                         cudaFuncAttributeMaxDynamicSharedMemorySize, smemS1);
    cudaFuncSetAttribute((const void*)gemm_sp<128, 64, 32, 32, 64, 0>,
                         cudaFuncAttributeMaxDynamicSharedMemorySize, smemB64);
    cudaFuncSetAttribute((const void*)gemm_sp<128, 64, 32, 32, 128, 6>,
                         cudaFuncAttributeMaxDynamicSharedMemorySize, smemS2);
    cudaFuncSetAttribute((const void*)gemm_sp<128, 64, 32, 32, 128, 7>,
                         cudaFuncAttributeMaxDynamicSharedMemorySize, smemS2);

    // fused prep
    prep_kernel<<<4224, 256>>>(
        W_dq, W_dkv, W_kr, b_dq, b_dkv, b_kr,
        W_uq, W_qr, b_uq, b_qr, W_uk, W_uv, b_uk, b_uv, W_o,
        ct, st, wcath, wcatl, bcat, w2qh, w2ql, b2q, w2kh, w2kl, b2k, woh, wol);

    // stage 1: fused down-projections (K=1024, N=320); A from fp32 x; k_r RoPE fused
    gemm_sp<64, 64, 16, 32, 64, 5><<<dim3(5, 128), 256, smemS1>>>(
        nullptr, nullptr, x, wcath, wcatl, bcat, 1.f, nullptr,
        cqh, cql, ckvh, ckvl, Kh, Kl, ct, st, M, 320, 1024);

    // stage 2 fused (single-shot K=128)
    gemm_sp<128, 64, 32, 32, 128, 6><<<dim3(24, 64), 256, smemS2>>>(
        cqh, cql, nullptr, w2qh, w2ql, b2q, SCALE_, nullptr, Qh, Ql, nullptr, nullptr,
        nullptr, nullptr, ct, st, M, 1536, 128);
    gemm_sp<128, 64, 32, 32, 128, 7><<<dim3(32, 64), 256, smemS2>>>(
        ckvh, ckvl, nullptr, w2kh, w2kl, b2k, 1.f, nullptr, Kh, Kl, Vh, Vl,
        nullptr, nullptr, nullptr, nullptr, M, 2048, 128);

    // flash attention -> split ao
    cudaFuncSetAttribute(flash_mma, cudaFuncAttributeMaxDynamicSharedMemorySize, FL_SMEM);
    flash_mma<<<dim3(Sn / 128, Bn * Hn), 256, FL_SMEM>>>(Qh, Ql, Kh, Kl, Vh, Vl, aoh, aol);

    // output projection (fp32 out + bias)
    gemm_sp<128, 64, 32, 32, 64, 0><<<dim3(16, 64), 256, smemB64>>>(
        aoh, aol, nullptr, woh, wol, b_o, 1.f, out, nullptr, nullptr, nullptr, nullptr,
        nullptr, nullptr, nullptr, nullptr, M, 1024, 1024);
}

// round 16
// speedup vs baseline: 1.0064x; 1.0064x over previous
#include <cuda_runtime.h>
#include <cuda_bf16.h>
#include <math.h>
#include <stdint.h>

typedef __nv_bfloat16 bf16;

// ---------------- problem constants ----------------
static constexpr int Bn  = 4;
static constexpr int Sn  = 2048;
static constexpr int Hn  = 16;
static constexpr int Mtot = Bn * Sn;  // 8192
static constexpr float SCALE_ = 0.10206207261596575f;  // 1/sqrt(96)

// ---------------- scratch (device globals) ----------------
__device__ bf16 g_cqh[Mtot * 128],  g_cql[Mtot * 128];
__device__ bf16 g_ckvh[Mtot * 128], g_ckvl[Mtot * 128];
__device__ bf16 g_Qh[(size_t)Bn * Hn * Sn * 96], g_Ql[(size_t)Bn * Hn * Sn * 96];
__device__ bf16 g_Kh[(size_t)Bn * Hn * Sn * 96], g_Kl[(size_t)Bn * Hn * Sn * 96];
__device__ bf16 g_Vh[(size_t)Bn * Hn * Sn * 64], g_Vl[(size_t)Bn * Hn * Sn * 64];
__device__ bf16 g_aoh[Mtot * 1024], g_aol[Mtot * 1024];
__device__ float g_cos[Sn * 16], g_sin[Sn * 16];
// packed split weights
__device__ bf16 g_wcath[1024 * 320], g_wcatl[1024 * 320];   // [W_dq | W_dkv | W_kr | 0]
__device__ float g_bcat[320];
__device__ bf16 g_w2qh[128 * 1536], g_w2ql[128 * 1536];     // [W_uq | W_qr]
__device__ float g_b2q[1536];
__device__ bf16 g_w2kh[128 * 2048], g_w2kl[128 * 2048];     // [W_uk | W_uv]
__device__ float g_b2k[2048];
__device__ bf16 g_woh[1024 * 1024], g_wol[1024 * 1024];

// ---------------- PTX helpers (baseline ISA only) ----------------
__device__ __forceinline__ uint32_t smem_u32(const void* p) {
    uint32_t a;
    asm("{ .reg .u64 t; cvta.to.shared.u64 t, %1; cvt.u32.u64 %0, t; }" : "=r"(a) : "l"(p));
    return a;
}
__device__ __forceinline__ void ldm4(uint32_t* r, uint32_t a) {
    asm volatile("ldmatrix.sync.aligned.m8n8.x4.shared.b16 {%0,%1,%2,%3}, [%4];"
                 : "=r"(r[0]), "=r"(r[1]), "=r"(r[2]), "=r"(r[3]) : "r"(a));
}
__device__ __forceinline__ void ldm4t(uint32_t* r, uint32_t a) {
    asm volatile("ldmatrix.sync.aligned.m8n8.x4.trans.shared.b16 {%0,%1,%2,%3}, [%4];"
                 : "=r"(r[0]), "=r"(r[1]), "=r"(r[2]), "=r"(r[3]) : "r"(a));
}
__device__ __forceinline__ void mma_b(float* d, const uint32_t* a, uint32_t b0, uint32_t b1) {
    asm volatile("mma.sync.aligned.m16n8k16.row.col.f32.bf16.bf16.f32 "
                 "{%0,%1,%2,%3}, {%4,%5,%6,%7}, {%8,%9}, {%0,%1,%2,%3};"
                 : "+f"(d[0]), "+f"(d[1]), "+f"(d[2]), "+f"(d[3])
                 : "r"(a[0]), "r"(a[1]), "r"(a[2]), "r"(a[3]), "r"(b0), "r"(b1));
}
__device__ __forceinline__ void cpa16(uint32_t dst, const void* src) {
    asm volatile("cp.async.cg.shared.global [%0], [%1], 16;" :: "r"(dst), "l"(src));
}
#define CP_COMMIT() asm volatile("cp.async.commit_group;" ::: "memory")
#define CP_WAIT0()  asm volatile("cp.async.wait_group 0;" ::: "memory")
#define CP_WAIT1()  asm volatile("cp.async.wait_group 1;" ::: "memory")

__device__ __forceinline__ uint32_t packbf(float x, float y) {
    __nv_bfloat162 t = __floats2bfloat162_rn(x, y);
    return *reinterpret_cast<uint32_t*>(&t);
}
__device__ __forceinline__ uint32_t packlo(float x, float y, uint32_t h) {
    __nv_bfloat162 hh = *reinterpret_cast<__nv_bfloat162*>(&h);
    float2 f = __bfloat1622float2(hh);
    return packbf(x - f.x, y - f.y);
}
__device__ __forceinline__ void cvt4(float4 v, uint2& h, uint2& l) {
    __nv_bfloat162 h0 = __floats2bfloat162_rn(v.x, v.y);
    __nv_bfloat162 h1 = __floats2bfloat162_rn(v.z, v.w);
    float2 f0 = __bfloat1622float2(h0), f1 = __bfloat1622float2(h1);
    __nv_bfloat162 l0 = __floats2bfloat162_rn(v.x - f0.x, v.y - f0.y);
    __nv_bfloat162 l1 = __floats2bfloat162_rn(v.z - f1.x, v.w - f1.y);
    h = make_uint2(*(uint32_t*)&h0, *(uint32_t*)&h1);
    l = make_uint2(*(uint32_t*)&l0, *(uint32_t*)&l1);
}

// ---------------- fused prep: rope tables + all weight packs + W_o split ----------
__global__ void prep_kernel(
    const float* __restrict__ Wdq, const float* __restrict__ Wdkv,
    const float* __restrict__ Wkr,
    const float* __restrict__ bdq, const float* __restrict__ bdkv,
    const float* __restrict__ bkr,
    const float* __restrict__ Wuq, const float* __restrict__ Wqr,
    const float* __restrict__ buq, const float* __restrict__ bqr,
    const float* __restrict__ Wuk, const float* __restrict__ Wuv,
    const float* __restrict__ buk, const float* __restrict__ buv,
    const float* __restrict__ Wo,
    float* __restrict__ ct, float* __restrict__ st,
    bf16* __restrict__ w1h, bf16* __restrict__ w1l, float* __restrict__ bcat,
    bf16* __restrict__ w2qh, bf16* __restrict__ w2ql, float* __restrict__ b2q,
    bf16* __restrict__ w2kh, bf16* __restrict__ w2kl, float* __restrict__ b2k,
    bf16* __restrict__ woh, bf16* __restrict__ wol) {
    const int blk = blockIdx.x, t = threadIdx.x;
    if (blk < 128) {
        int i = blk * 256 + t;
        int s = i >> 4, p = i & 15;
        float inv = powf(10000.f, -(float)p / 16.f);
        float c, sn;
        sincosf((float)s * inv, &sn, &c);
        ct[i] = c; st[i] = sn;
    } else if (blk < 1408) {
        int idx = (blk - 128) * 256 + t;
        if (idx < 320)
            bcat[idx] = idx < 128 ? bdq[idx]
                      : (idx < 256 ? bdkv[idx - 128] : (idx < 288 ? bkr[idx - 256] : 0.f));
        if (idx >= 1024 * 320) return;
        int k = idx / 320, n = idx % 320;
        float v = n < 128 ? Wdq[k * 128 + n]
                : (n < 256 ? Wdkv[k * 128 + n - 128]
                : (n < 288 ? Wkr[k * 32 + n - 256] : 0.f));
        bf16 h = __float2bfloat16_rn(v);
        w1h[idx] = h;
        w1l[idx] = __float2bfloat16_rn(v - __bfloat162float(h));
    } else if (blk < 2176) {
        int idx = (blk - 1408) * 256 + t;
        if (idx < 1536) b2q[idx] = idx < 1024 ? buq[idx] : bqr[idx - 1024];
        int k = idx / 1536, n = idx % 1536;
        float v = n < 1024 ? Wuq[k * 1024 + n] : Wqr[k * 512 + (n - 1024)];
        bf16 h = __float2bfloat16_rn(v);
        w2qh[idx] = h;
        w2ql[idx] = __float2bfloat16_rn(v - __bfloat162float(h));
    } else if (blk < 3200) {
        int idx = (blk - 2176) * 256 + t;
        if (idx < 2048) b2k[idx] = idx < 1024 ? buk[idx] : buv[idx - 1024];
        int k = idx / 2048, n = idx % 2048;
        float v = n < 1024 ? Wuk[k * 1024 + n] : Wuv[k * 1024 + (n - 1024)];
        bf16 h = __float2bfloat16_rn(v);
        w2kh[idx] = h;
        w2kl[idx] = __float2bfloat16_rn(v - __bfloat162float(h));
    } else {
        int i = ((blk - 3200) * 256 + t) * 4;
        float4 v = *(const float4*)(Wo + i);
        uint2 h, l; cvt4(v, h, l);
        *(uint2*)(woh + i) = h;
        *(uint2*)(wol + i) = l;
    }
}

// ---------------- split-bf16 mma.sync GEMM, BK=64, 2-stage cp.async ----------
// MODE 0: fp32 out (+bias)
// MODE 5: fused stage-1: A from fp32 x (reg-pipelined cvt); routing epilogue
// MODE 8: fused stage-2 (blockIdx.z: 0 -> q [content+rope], 1 -> kv [K content + V]),
//         operands taken from device globals.
template <int BM, int BN, int WM, int WN, int MODE>
__global__ void __launch_bounds__(256)
gemm_sp(const bf16* __restrict__ Ah0, const bf16* __restrict__ Al0,
        const float* __restrict__ Af,
        const bf16* __restrict__ Bh0, const bf16* __restrict__ Bl0,
        const float* __restrict__ bias0, float scale,
        float* __restrict__ Cf, bf16* __restrict__ Coh, bf16* __restrict__ Col,
        bf16* __restrict__ Coh2, bf16* __restrict__ Col2,
        bf16* __restrict__ Koh, bf16* __restrict__ Kol,
        const float* __restrict__ ct, const float* __restrict__ st,
        int M, int N0, int K) {
    constexpr int BK = 64, ASTR = BK + 8, BSTR = BN + 8;
    constexpr int MI = WM / 16, NI = WN / 8, WNC = BN / WN;
    constexpr int ASZ = BM * ASTR, BSZ = BK * BSTR;
    constexpr int STG = 2 * (ASZ + BSZ);
    constexpr int KQ = BK / 8;
    constexpr int NAR = BM * BK / (4 * 256);

    // MODE 8 operand selection (uniform per block)
    const bf16* Ah = Ah0; const bf16* Al = Al0;
    const bf16* Bh = Bh0; const bf16* Bl = Bl0;
    const float* bias = bias0;
    int N = N0;
    int zsel = 0;
    if constexpr (MODE == 8) {
        zsel = blockIdx.z;
        if (zsel == 0 && blockIdx.x >= 24) return;  // q grid is 24 wide
        if (zsel == 0) { Ah = g_cqh;  Al = g_cql;  Bh = g_w2qh; Bl = g_w2ql; bias = g_b2q; N = 1536; }
        else           { Ah = g_ckvh; Al = g_ckvl; Bh = g_w2kh; Bl = g_w2kl; bias = g_b2k; N = 2048; }
    }

    extern __shared__ bf16 smg[];
    const int tid = threadIdx.x, lane = tid & 31, wid = tid >> 5;
    const int wm0 = (wid / WNC) * WM, wn0 = (wid % WNC) * WN;
    const int m0 = blockIdx.y * BM, n0 = blockIdx.x * BN;
    const uint32_t sb = smem_u32(smg);

    float acc[MI][NI][4];
#pragma unroll
    for (int i = 0; i < MI; i++)
#pragma unroll
        for (int j = 0; j < NI; j++)
#pragma unroll
            for (int q = 0; q < 4; q++) acc[i][j][q] = 0.f;

    const int nch = K / BK;

    auto load_B = [&](int stg, int c) {
        uint32_t pBH = sb + (uint32_t)(stg * STG + 2 * ASZ) * 2;
        uint32_t pBL = pBH + BSZ * 2;
        const bf16* gBh = Bh + (size_t)(c * BK) * N + n0;
        const bf16* gBl = Bl + (size_t)(c * BK) * N + n0;
#pragma unroll
        for (int f = tid; f < BK * (BN / 8); f += 256) {
            int k = f / (BN / 8), n8 = (f % (BN / 8)) * 8;
            uint32_t d = (uint32_t)(k * BSTR + n8) * 2;
            cpa16(pBH + d, gBh + (size_t)k * N + n8);
            cpa16(pBL + d, gBl + (size_t)k * N + n8);
        }
    };
    auto load_A = [&](int stg, int c) {
        uint32_t pAH = sb + (uint32_t)(stg * STG) * 2;
        uint32_t pAL = pAH + ASZ * 2;
        const bf16* gAh = Ah + (size_t)m0 * K + c * BK;
        const bf16* gAl = Al + (size_t)m0 * K + c * BK;
#pragma unroll
        for (int f = tid; f < BM * KQ; f += 256) {
            int m = f / KQ, k8 = (f % KQ) * 8;
            uint32_t d = (uint32_t)(m * ASTR + k8) * 2;
            cpa16(pAH + d, gAh + (size_t)m * K + k8);
            cpa16(pAL + d, gAl + (size_t)m * K + k8);
        }
    };

    float4 Areg[NAR > 0 ? NAR : 1];
    auto ldA_f32 = [&](int c) {
        const float* g = Af + (size_t)m0 * K + c * BK;
#pragma unroll
        for (int i = 0; i < NAR; i++) {
            int f = tid + i * 256;
            int m = f / (BK / 4), k4 = (f % (BK / 4)) * 4;
            Areg[i] = *(const float4*)(g + (size_t)m * K + k4);
        }
    };

    if constexpr (MODE == 5) {
        ldA_f32(0);
        load_B(0, 0);
        CP_COMMIT();
    } else {
        load_A(0, 0);
        load_B(0, 0);
        CP_COMMIT();
    }

    for (int c = 0; c < nch; c++) {
        const int cur = c & 1;
        if constexpr (MODE == 5) {
            {
                uint32_t pAH = sb + (uint32_t)(cur * STG) * 2;
                uint32_t pAL = pAH + ASZ * 2;
#pragma unroll
                for (int i = 0; i < NAR; i++) {
                    int f = tid + i * 256;
                    int m = f / (BK / 4), k4 = (f % (BK / 4)) * 4;
                    uint2 h, l; cvt4(Areg[i], h, l);
                    uint32_t d = (uint32_t)(m * ASTR + k4) * 2;
                    asm volatile("st.shared.v2.b32 [%0], {%1, %2};" :: "r"(pAH + d), "r"(h.x), "r"(h.y));
                    asm volatile("st.shared.v2.b32 [%0], {%1, %2};" :: "r"(pAL + d), "r"(l.x), "r"(l.y));
                }
            }
            if (c + 1 < nch) { ldA_f32(c + 1); load_B(cur ^ 1, c + 1); CP_COMMIT(); CP_WAIT1(); }
            else             { CP_WAIT0(); }
        } else {
            if (c + 1 < nch) { load_A(cur ^ 1, c + 1); load_B(cur ^ 1, c + 1); CP_COMMIT(); CP_WAIT1(); }
            else             { CP_WAIT0(); }
        }
        __syncthreads();

        const uint32_t base = sb + (uint32_t)(cur * STG) * 2;
        const uint32_t aAH = base;
        const uint32_t aAL = aAH + ASZ * 2;
        const uint32_t aBH = aAL + ASZ * 2;
        const uint32_t aBL = aBH + BSZ * 2;

#pragma unroll
        for (int kk = 0; kk < BK; kk += 16) {
            uint32_t aH[MI][4], aL[MI][4];
#pragma unroll
            for (int mi = 0; mi < MI; mi++) {
                uint32_t off = (uint32_t)((wm0 + mi * 16 + (lane & 15)) * ASTR
                                          + kk + ((lane >> 4) << 3)) * 2;
                ldm4(aH[mi], aAH + off);
                ldm4(aL[mi], aAL + off);
            }
            uint32_t bH[NI][2], bL[NI][2];
#pragma unroll
            for (int nj = 0; nj < NI / 2; nj++) {
                uint32_t off = (uint32_t)((kk + ((lane >> 4) << 3) + (lane & 7)) * BSTR
                                          + wn0 + nj * 16 + (((lane >> 3) & 1) << 3)) * 2;
                uint32_t r[4];
                ldm4t(r, aBH + off);
                bH[2 * nj][0] = r[0]; bH[2 * nj][1] = r[2];
                bH[2 * nj + 1][0] = r[1]; bH[2 * nj + 1][1] = r[3];
                ldm4t(r, aBL + off);
                bL[2 * nj][0] = r[0]; bL[2 * nj][1] = r[2];
                bL[2 * nj + 1][0] = r[1]; bL[2 * nj + 1][1] = r[3];
            }
#pragma unroll
            for (int mi = 0; mi < MI; mi++)
#pragma unroll
                for (int ni = 0; ni < NI; ni++) {
                    mma_b(acc[mi][ni], aH[mi], bH[ni][0], bH[ni][1]);
                    mma_b(acc[mi][ni], aH[mi], bL[ni][0], bL[ni][1]);
                    mma_b(acc[mi][ni], aL[mi], bH[ni][0], bH[ni][1]);
                }
        }
        __syncthreads();
    }

    // ---------------- fused epilogue ----------------
#pragma unroll
    for (int mi = 0; mi < MI; mi++) {
        int r0 = m0 + wm0 + mi * 16 + (lane >> 2);
#pragma unroll
        for (int ni = 0; ni < NI; ni++) {
            int cc = n0 + wn0 + ni * 8 + (lane & 3) * 2;
            float bx = bias[cc], by = bias[cc + 1];
            float x0 = acc[mi][ni][0] + bx, y0 = acc[mi][ni][1] + by;
            float x1 = acc[mi][ni][2] + bx, y1 = acc[mi][ni][3] + by;

            if constexpr (MODE == 0) {
                *(float2*)(Cf + (size_t)r0 * N + cc) = make_float2(x0, y0);
                *(float2*)(Cf + (size_t)(r0 + 8) * N + cc) = make_float2(x1, y1);
            } else if constexpr (MODE == 5) {
                if (cc < 128) {
                    size_t d0 = (size_t)r0 * 128 + cc;
                    size_t d1 = d0 + (size_t)8 * 128;
                    uint32_t hh = packbf(x0, y0);
                    *(uint32_t*)(Coh + d0) = hh;
                    *(uint32_t*)(Col + d0) = packlo(x0, y0, hh);
                    hh = packbf(x1, y1);
                    *(uint32_t*)(Coh + d1) = hh;
                    *(uint32_t*)(Col + d1) = packlo(x1, y1, hh);
                } else if (cc < 256) {
                    size_t d0 = (size_t)r0 * 128 + (cc - 128);
                    size_t d1 = d0 + (size_t)8 * 128;
                    uint32_t hh = packbf(x0, y0);
                    *(uint32_t*)(Coh2 + d0) = hh;
                    *(uint32_t*)(Col2 + d0) = packlo(x0, y0, hh);
                    hh = packbf(x1, y1);
                    *(uint32_t*)(Coh2 + d1) = hh;
                    *(uint32_t*)(Col2 + d1) = packlo(x1, y1, hh);
                } else if (cc < 288) {
                    int b = r0 >> 11, s = r0 & 2047;
                    int pp = cc - 256, p = pp >> 1;
                    float c0 = ct[s * 16 + p], s0 = st[s * 16 + p];
                    float k0 = x0 * c0 - y0 * s0, k1 = x0 * s0 + y0 * c0;
                    uint32_t hh0 = packbf(k0, k1), ll0 = packlo(k0, k1, hh0);
                    float c1 = ct[(s + 8) * 16 + p], s1 = st[(s + 8) * 16 + p];
                    k0 = x1 * c1 - y1 * s1; k1 = x1 * s1 + y1 * c1;
                    uint32_t hh1 = packbf(k0, k1), ll1 = packlo(k0, k1, hh1);
                    size_t rowb = ((size_t)(b * Hn) * Sn + s) * 96 + 64 + pp;
#pragma unroll
                    for (int h = 0; h < Hn; h++) {
                        size_t d0 = rowb + (size_t)h * Sn * 96;
                        *(uint32_t*)(Koh + d0) = hh0;
                        *(uint32_t*)(Kol + d0) = ll0;
                        *(uint32_t*)(Koh + d0 + 8 * 96) = hh1;
                        *(uint32_t*)(Kol + d0 + 8 * 96) = ll1;
                    }
                }
            } else {  // MODE 8: fused stage-2 (z=0: q, z=1: kv)
                int b = r0 >> 11, s = r0 & 2047;
                if (zsel == 0) {
                    if (cc < 1024) {
                        int h = cc >> 6, d = cc & 63;
                        size_t d0 = ((size_t)((b * Hn + h) * Sn) + s) * 96 + d;
                        size_t d1 = d0 + (size_t)8 * 96;
                        x0 *= SCALE_; y0 *= SCALE_; x1 *= SCALE_; y1 *= SCALE_;
                        uint32_t hh = packbf(x0, y0);
                        *(uint32_t*)(g_Qh + d0) = hh;
                        *(uint32_t*)(g_Ql + d0) = packlo(x0, y0, hh);
                        hh = packbf(x1, y1);
                        *(uint32_t*)(g_Qh + d1) = hh;
                        *(uint32_t*)(g_Ql + d1) = packlo(x1, y1, hh);
                    } else {
                        int c2 = cc - 1024;
                        int h = c2 >> 5, pp = c2 & 31, p = pp >> 1;
                        size_t d0 = ((size_t)((b * Hn + h) * Sn) + s) * 96 + 64 + pp;
                        size_t d1 = d0 + (size_t)8 * 96;
                        float c0 = ct[s * 16 + p], s0 = st[s * 16 + p];
                        float xr = (x0 * c0 - y0 * s0) * SCALE_;
                        float yr = (x0 * s0 + y0 * c0) * SCALE_;
                        uint32_t hh = packbf(xr, yr);
                        *(uint32_t*)(g_Qh + d0) = hh;
                        *(uint32_t*)(g_Ql + d0) = packlo(xr, yr, hh);
                        float c1 = ct[(s + 8) * 16 + p], s1 = st[(s + 8) * 16 + p];
                        xr = (x1 * c1 - y1 * s1) * SCALE_;
                        yr = (x1 * s1 + y1 * c1) * SCALE_;
                        hh = packbf(xr, yr);
                        *(uint32_t*)(g_Qh + d1) = hh;
                        *(uint32_t*)(g_Ql + d1) = packlo(xr, yr, hh);
                    }
                } else {
                    if (cc < 1024) {
                        int h = cc >> 6, d = cc & 63;
                        size_t d0 = ((size_t)((b * Hn + h) * Sn) + s) * 96 + d;
                        size_t d1 = d0 + (size_t)8 * 96;
                        uint32_t hh = packbf(x0, y0);
                        *(uint32_t*)(g_Kh + d0) = hh;
                        *(uint32_t*)(g_Kl + d0) = packlo(x0, y0, hh);
                        hh = packbf(x1, y1);
                        *(uint32_t*)(g_Kh + d1) = hh;
                        *(uint32_t*)(g_Kl + d1) = packlo(x1, y1, hh);
                    } else {
                        int c2 = cc - 1024;
                        int h = c2 >> 6, d = c2 & 63;
                        size_t d0 = ((size_t)((b * Hn + h) * Sn) + s) * 64 + d;
                        size_t d1 = d0 + (size_t)8 * 64;
                        uint32_t hh = packbf(x0, y0);
                        *(uint32_t*)(g_Vh + d0) = hh;
                        *(uint32_t*)(g_Vl + d0) = packlo(x0, y0, hh);
                        hh = packbf(x1, y1);
                        *(uint32_t*)(g_Vh + d1) = hh;
                        *(uint32_t*)(g_Vl + d1) = packlo(x1, y1, hh);
                    }
                }
            }
        }
    }
}

// ---------------- flash attention: deferred-consume pipeline, 3 KV buffers ----------
static constexpr int QSf = 104;
static constexpr int VSf = 72;
static constexpr int FL_UQ = 2 * 128 * QSf;
static constexpr int U_KV  = 2 * 64 * QSf + 2 * 64 * VSf;
static constexpr int FL_SMEM = (FL_UQ + 3 * U_KV) * 2;

__global__ void __launch_bounds__(256, 1)
flash_mma(const bf16* __restrict__ Qh, const bf16* __restrict__ Ql,
          const bf16* __restrict__ Kh, const bf16* __restrict__ Kl,
          const bf16* __restrict__ Vh, const bf16* __restrict__ Vl,
          bf16* __restrict__ Ooh, bf16* __restrict__ Ool) {
    extern __shared__ bf16 sm[];

    const int qt = gridDim.x - 1 - blockIdx.x;
    const int bh = blockIdx.y;
    const int tid = threadIdx.x, lane = tid & 31, wid = tid >> 5;
    const int wm = wid * 16;

    const uint32_t sb = smem_u32(sm);
    const uint32_t aQh = sb;
    const uint32_t aQl = aQh + 128 * QSf * 2;

    {
        const bf16* gQh = Qh + ((size_t)bh * Sn + (size_t)qt * 128) * 96;
        const bf16* gQl = Ql + ((size_t)bh * Sn + (size_t)qt * 128) * 96;
#pragma unroll
        for (int f = tid; f < 128 * 12; f += 256) {
            int r = f / 12, c = (f % 12) * 8;
            uint32_t d = (uint32_t)(r * QSf + c) * 2;
            cpa16(aQh + d, gQh + (size_t)r * 96 + c);
            cpa16(aQl + d, gQl + (size_t)r * 96 + c);
        }
        CP_COMMIT();
    }

    auto kvb = [&](int buf) -> uint32_t {
        return sb + (uint32_t)(FL_UQ + buf * U_KV) * 2;
    };
    auto loadKV = [&](int buf, int kt) {
        uint32_t pKh = kvb(buf);
        uint32_t pKl = pKh + (uint32_t)(64 * QSf) * 2;
        uint32_t pVh = pKh + (uint32_t)(2 * 64 * QSf) * 2;
        uint32_t pVl = pVh + (uint32_t)(64 * VSf) * 2;
        const bf16* gKh = Kh + ((size_t)bh * Sn + (size_t)kt * 64) * 96;
        const bf16* gKl = Kl + ((size_t)bh * Sn + (size_t)kt * 64) * 96;
#pragma unroll
        for (int f = tid; f < 64 * 12; f += 256) {
            int r = f / 12, c = (f % 12) * 8;
            uint32_t d = (uint32_t)(r * QSf + c) * 2;
            cpa16(pKh + d, gKh + (size_t)r * 96 + c);
            cpa16(pKl + d, gKl + (size_t)r * 96 + c);
        }
        const bf16* gVh = Vh + ((size_t)bh * Sn + (size_t)kt * 64) * 64;
        const bf16* gVl = Vl + ((size_t)bh * Sn + (size_t)kt * 64) * 64;
#pragma unroll
        for (int f = tid; f < 64 * 8; f += 256) {
            int r = f >> 3, c = (f & 7) * 8;
            uint32_t d = (uint32_t)(r * VSf + c) * 2;
            cpa16(pVh + d, gVh + (size_t)r * 64 + c);
            cpa16(pVl + d, gVl + (size_t)r * 64 + c);
        }
    };

    loadKV(0, 0);
    CP_COMMIT();

    CP_WAIT1();
    __syncthreads();
    uint32_t qhr[6][4], qlr[6][4];
#pragma unroll
    for (int kk = 0; kk < 6; kk++) {
        uint32_t qoff = (uint32_t)((wm + (lane & 15)) * QSf + kk * 16 + ((lane >> 4) << 3)) * 2;
        ldm4(qhr[kk], aQh + qoff);
        ldm4(qlr[kk], aQl + qoff);
    }

    float m0r = -1e30f, m1r = -1e30f, l0r = 0.f, l1r = 0.f;
    float acc[8][4];
#pragma unroll
    for (int i = 0; i < 8; i++)
#pragma unroll
        for (int q = 0; q < 4; q++) acc[i][q] = 0.f;
    float Sp[8][4];

    auto consume = [&](int pbuf) {
        float mt0 = -1e30f, mt1 = -1e30f;
#pragma unroll
        for (int ni = 0; ni < 8; ni++) {
            mt0 = fmaxf(mt0, fmaxf(Sp[ni][0], Sp[ni][1]));
            mt1 = fmaxf(mt1, fmaxf(Sp[ni][2], Sp[ni][3]));
        }
        mt0 = fmaxf(mt0, __shfl_xor_sync(0xffffffff, mt0, 1));
        mt0 = fmaxf(mt0, __shfl_xor_sync(0xffffffff, mt0, 2));
        mt1 = fmaxf(mt1, __shfl_xor_sync(0xffffffff, mt1, 1));
        mt1 = fmaxf(mt1, __shfl_xor_sync(0xffffffff, mt1, 2));
        float mn0 = fmaxf(m0r, mt0), mn1 = fmaxf(m1r, mt1);
        float al0 = __expf(m0r - mn0), al1 = __expf(m1r - mn1);
        m0r = mn0; m1r = mn1;

        float s0 = 0.f, s1 = 0.f;
#pragma unroll
        for (int ni = 0; ni < 8; ni++) {
            Sp[ni][0] = __expf(Sp[ni][0] - mn0); s0 += Sp[ni][0];
            Sp[ni][1] = __expf(Sp[ni][1] - mn0); s0 += Sp[ni][1];
            Sp[ni][2] = __expf(Sp[ni][2] - mn1); s1 += Sp[ni][2];
            Sp[ni][3] = __expf(Sp[ni][3] - mn1); s1 += Sp[ni][3];
        }
        s0 += __shfl_xor_sync(0xffffffff, s0, 1);
        s0 += __shfl_xor_sync(0xffffffff, s0, 2);
        s1 += __shfl_xor_sync(0xffffffff, s1, 1);
        s1 += __shfl_xor_sync(0xffffffff, s1, 2);
        l0r = l0r * al0 + s0;
        l1r = l1r * al1 + s1;
#pragma unroll
        for (int ni = 0; ni < 8; ni++) {
            acc[ni][0] *= al0; acc[ni][1] *= al0;
            acc[ni][2] *= al1; acc[ni][3] *= al1;
        }

        const uint32_t bVh = kvb(pbuf) + (uint32_t)(2 * 64 * QSf) * 2;
        const uint32_t bVl = bVh + (uint32_t)(64 * VSf) * 2;
#pragma unroll
        for (int kp = 0; kp < 4; kp++) {
            uint32_t ah[4], alr[4];
            ah[0]  = packbf(Sp[2 * kp][0],     Sp[2 * kp][1]);
            alr[0] = packlo(Sp[2 * kp][0],     Sp[2 * kp][1],     ah[0]);
            ah[1]  = packbf(Sp[2 * kp][2],     Sp[2 * kp][3]);
            alr[1] = packlo(Sp[2 * kp][2],     Sp[2 * kp][3],     ah[1]);
            ah[2]  = packbf(Sp[2 * kp + 1][0], Sp[2 * kp + 1][1]);
            alr[2] = packlo(Sp[2 * kp + 1][0], Sp[2 * kp + 1][1], ah[2]);
            ah[3]  = packbf(Sp[2 * kp + 1][2], Sp[2 * kp + 1][3]);
            alr[3] = packlo(Sp[2 * kp + 1][2], Sp[2 * kp + 1][3], ah[3]);
#pragma unroll
            for (int ng = 0; ng < 4; ng++) {
                uint32_t voff = (uint32_t)((kp * 16 + (lane & 7) + ((lane >> 4) << 3)) * VSf
                                           + ng * 16 + (((lane >> 3) & 1) << 3)) * 2;
                uint32_t vh[4], vl[4];
                ldm4t(vh, bVh + voff);
                ldm4t(vl, bVl + voff);
                mma_b(acc[2 * ng],     ah,  vh[0], vh[2]);
                mma_b(acc[2 * ng],     ah,  vl[0], vl[2]);
                mma_b(acc[2 * ng],     alr, vh[0], vh[2]);
                mma_b(acc[2 * ng + 1], ah,  vh[1], vh[3]);
                mma_b(acc[2 * ng + 1], ah,  vl[1], vl[3]);
                mma_b(acc[2 * ng + 1], alr, vh[1], vh[3]);
            }
        }
    };

    const int nkt = 2 * qt + 2;
    int cur = 0;
    for (int kt = 0; kt < nkt; kt++) {
        const int nxt = (cur == 2) ? 0 : cur + 1;
        const int prv = (cur == 0) ? 2 : cur - 1;
        if (kt + 1 < nkt) { loadKV(nxt, kt + 1); CP_COMMIT(); CP_WAIT1(); }
        else              { CP_WAIT0(); }
        __syncthreads();

        const uint32_t bKh = kvb(cur);
        const uint32_t bKl = bKh + (uint32_t)(64 * QSf) * 2;
        float S[8][4];
#pragma unroll
        for (int i = 0; i < 8; i++)
#pragma unroll
            for (int q = 0; q < 4; q++) S[i][q] = 0.f;

#pragma unroll
        for (int kk = 0; kk < 6; kk++) {
#pragma unroll
            for (int ng = 0; ng < 4; ng++) {
                uint32_t koff = (uint32_t)((ng * 16 + (lane & 7) + ((lane >> 4) << 3)) * QSf
                                           + kk * 16 + (((lane >> 3) & 1) << 3)) * 2;
                uint32_t kh[4], kl[4];
                ldm4(kh, bKh + koff);
                ldm4(kl, bKl + koff);
                mma_b(S[2 * ng],     qhr[kk], kh[0], kh[1]);
                mma_b(S[2 * ng],     qhr[kk], kl[0], kl[1]);
                mma_b(S[2 * ng],     qlr[kk], kh[0], kh[1]);
                mma_b(S[2 * ng + 1], qhr[kk], kh[2], kh[3]);
                mma_b(S[2 * ng + 1], qhr[kk], kl[2], kl[3]);
                mma_b(S[2 * ng + 1], qlr[kk], kh[2], kh[3]);
            }
        }

        if (kt >= 2 * qt) {
            int qrow0 = qt * 128 + wm + (lane >> 2);
            int kbase = kt * 64 + (lane & 3) * 2;
#pragma unroll
            for (int ni = 0; ni < 8; ni++) {
                int kc = kbase + ni * 8;
                if (kc > qrow0)         S[ni][0] = -1e30f;
                if (kc + 1 > qrow0)     S[ni][1] = -1e30f;
                if (kc > qrow0 + 8)     S[ni][2] = -1e30f;
                if (kc + 1 > qrow0 + 8) S[ni][3] = -1e30f;
            }
        }

        if (kt > 0) consume(prv);

#pragma unroll
        for (int i = 0; i < 8; i++)
#pragma unroll
            for (int q = 0; q < 4; q++) Sp[i][q] = S[i][q];

        cur = nxt;
    }
    consume((cur == 0) ? 2 : cur - 1);

    const int b = bh >> 4, h = bh & 15;
    float inv0 = 1.f / l0r, inv1 = 1.f / l1r;
    int r0 = qt * 128 + wm + (lane >> 2);
    size_t base0 = ((size_t)b * Sn + r0) * 1024 + h * 64 + (lane & 3) * 2;
    size_t base1 = base0 + (size_t)8 * 1024;
#pragma unroll
    for (int ni = 0; ni < 8; ni++) {
        float x = acc[ni][0] * inv0, y = acc[ni][1] * inv0;
        uint32_t hh = packbf(x, y);
        *(uint32_t*)(Ooh + base0 + ni * 8) = hh;
        *(uint32_t*)(Ool + base0 + ni * 8) = packlo(x, y, hh);
        x = acc[ni][2] * inv1; y = acc[ni][3] * inv1;
        hh = packbf(x, y);
        *(uint32_t*)(Ooh + base1 + ni * 8) = hh;
        *(uint32_t*)(Ool + base1 + ni * 8) = packlo(x, y, hh);
    }
}

// ---------------- launch ----------------
extern "C" void kernel_launch(void* const* d_in, const int* in_sizes, int n_in,
                              void* d_out, int out_size) {
    const float* x     = (const float*)d_in[0];
    // d_in[1] = mask: tril of ones -> uniform +1 on allowed entries; softmax is
    // shift-invariant -> plain causal masking. Unused.
    const float* W_dkv = (const float*)d_in[2];
    const float* b_dkv = (const float*)d_in[3];
    const float* W_dq  = (const float*)d_in[4];
    const float* b_dq  = (const float*)d_in[5];
    const float* W_uk  = (const float*)d_in[6];
    const float* b_uk  = (const float*)d_in[7];
    const float* W_uv  = (const float*)d_in[8];
    const float* b_uv  = (const float*)d_in[9];
    const float* W_uq  = (const float*)d_in[10];
    const float* b_uq  = (const float*)d_in[11];
    const float* W_qr  = (const float*)d_in[12];
    const float* b_qr  = (const float*)d_in[13];
    const float* W_kr  = (const float*)d_in[14];
    const float* b_kr  = (const float*)d_in[15];
    const float* W_o   = (const float*)d_in[16];
    const float* b_o   = (const float*)d_in[17];
    float* out = (float*)d_out;

    bf16 *cqh, *cql, *ckvh, *ckvl, *Qh, *Ql, *Kh, *Kl, *Vh, *Vl, *aoh, *aol;
    bf16 *wcath, *wcatl, *w2qh, *w2ql, *w2kh, *w2kl, *woh, *wol;
    float *ct, *st, *bcat, *b2q, *b2k;
    cudaGetSymbolAddress((void**)&cqh, g_cqh); cudaGetSymbolAddress((void**)&cql, g_cql);
    cudaGetSymbolAddress((void**)&ckvh, g_ckvh); cudaGetSymbolAddress((void**)&ckvl, g_ckvl);
    cudaGetSymbolAddress((void**)&Qh, g_Qh);   cudaGetSymbolAddress((void**)&Ql, g_Ql);
    cudaGetSymbolAddress((void**)&Kh, g_Kh);   cudaGetSymbolAddress((void**)&Kl, g_Kl);
    cudaGetSymbolAddress((void**)&Vh, g_Vh);   cudaGetSymbolAddress((void**)&Vl, g_Vl);
    cudaGetSymbolAddress((void**)&aoh, g_aoh); cudaGetSymbolAddress((void**)&aol, g_aol);
    cudaGetSymbolAddress((void**)&ct, g_cos);  cudaGetSymbolAddress((void**)&st, g_sin);
    cudaGetSymbolAddress((void**)&wcath, g_wcath); cudaGetSymbolAddress((void**)&wcatl, g_wcatl);
    cudaGetSymbolAddress((void**)&bcat, g_bcat);
    cudaGetSymbolAddress((void**)&w2qh, g_w2qh);   cudaGetSymbolAddress((void**)&w2ql, g_w2ql);
    cudaGetSymbolAddress((void**)&b2q, g_b2q);
    cudaGetSymbolAddress((void**)&w2kh, g_w2kh);   cudaGetSymbolAddress((void**)&w2kl, g_w2kl);
    cudaGetSymbolAddress((void**)&b2k, g_b2k);
    cudaGetSymbolAddress((void**)&woh, g_woh);     cudaGetSymbolAddress((void**)&wol, g_wol);

    const int M = Mtot;

    // smem: 2 stages * 2*(BM*(BK+8) + BK*(BN+8)) units * 2B, BK=64
    const int smemB64 = 2 * 2 * (128 * 72 + 64 * 72) * 2;  // 110592 (BM128,BN64)
    const int smemS1  = 2 * 2 * (64 * 72 + 64 * 72) * 2;   //  73728 (BM64,BN64)
    cudaFuncSetAttribute((const void*)gemm_sp<64, 64, 16, 32, 5>,
                         cudaFuncAttributeMaxDynamicSharedMemorySize, smemS1);
    cudaFuncSetAttribute((const void*)gemm_sp<128, 64, 32, 32, 0>,
                         cudaFuncAttributeMaxDynamicSharedMemorySize, smemB64);
    cudaFuncSetAttribute((const void*)gemm_sp<128, 64, 32, 32, 8>,
                         cudaFuncAttributeMaxDynamicSharedMemorySize, smemB64);

    // fused prep: rope tables + all weight packs + W_o split (one launch)
    prep_kernel<<<4224, 256>>>(
        W_dq, W_dkv, W_kr, b_dq, b_dkv, b_kr,
        W_uq, W_qr, b_uq, b_qr, W_uk, W_uv, b_uk, b_uv, W_o,
        ct, st, wcath, wcatl, bcat, w2qh, w2ql, b2q, w2kh, w2kl, b2k, woh, wol);

    // stage 1: fused down-projections (K=1024, N=320); A from fp32 x; k_r RoPE fused
    gemm_sp<64, 64, 16, 32, 5><<<dim3(5, 128), 256, smemS1>>>(
        nullptr, nullptr, x, wcath, wcatl, bcat, 1.f, nullptr,
        cqh, cql, ckvh, ckvl, Kh, Kl, ct, st, M, 320, 1024);

    // stage 2: q + kv fused into ONE launch (z=0: q over 24 x-blocks; z=1: kv over 32)
    gemm_sp<128, 64, 32, 32, 8><<<dim3(32, 64, 2), 256, smemB64>>>(
        nullptr, nullptr, nullptr, nullptr, nullptr, nullptr, 1.f, nullptr,
        nullptr, nullptr, nullptr, nullptr, nullptr, nullptr, ct, st, M, 0, 128);

    // flash attention -> split ao (deferred-consume pipeline)
    cudaFuncSetAttribute(flash_mma, cudaFuncAttributeMaxDynamicSharedMemorySize, FL_SMEM);
    flash_mma<<<dim3(Sn / 128, Bn * Hn), 256, FL_SMEM>>>(Qh, Ql, Kh, Kl, Vh, Vl, aoh, aol);

    // output projection (fp32 out + bias)
    gemm_sp<128, 64, 32, 32, 0><<<dim3(16, 64), 256, smemB64>>>(
        aoh, aol, nullptr, woh, wol, b_o, 1.f, out, nullptr, nullptr, nullptr, nullptr,
        nullptr, nullptr, nullptr, nullptr, M, 1024, 1024);
}